// round 1
// baseline (speedup 1.0000x reference)
#include <cuda_runtime.h>
#include <math.h>

// ---------------------------------------------------------------------------
// Problem constants (shapes fixed by setup_inputs)
// ---------------------------------------------------------------------------
#define HF 480
#define WF 640
#define NPXF (HF * WF)
#define B_MAX 2

// ---------------------------------------------------------------------------
// Scratch (static device globals; no allocation allowed)
// ---------------------------------------------------------------------------
__device__ float g_Is [B_MAX * 3 * (NPXF / 4)];   // resized I (s>=2 only)
__device__ float g_Es [B_MAX * (NPXF / 4)];       // resized+clipped E (s>=2 only)
__device__ float g_DLs[B_MAX * (NPXF / 4)];
__device__ float g_MLs[B_MAX * (NPXF / 4)];
__device__ float g_D0 [B_MAX * NPXF];
__device__ float g_D1 [B_MAX * NPXF];
__device__ float g_up [B_MAX * NPXF];
__device__ float g_x  [B_MAX * 6  * NPXF];
__device__ float g_f1 [B_MAX * 64 * NPXF];
__device__ float g_f2 [B_MAX * 64 * NPXF];
__device__ float g_kap[B_MAX * 65 * NPXF];
__device__ float g_A  [B_MAX * 24 * NPXF];
__device__ float g_t3 [B_MAX * 3  * NPXF];
__device__ float g_pk [B_MAX * 36 * NPXF];        // packed per-pixel params

__device__ __forceinline__ float clamp01f(float v) { return fminf(fmaxf(v, 0.0f), 1.0f); }

// ---------------------------------------------------------------------------
// Antialiased bilinear downsample by integer factor f (2 or 4).
// Matches jax.image.resize(method='linear', antialias=True): triangle kernel of
// half-width f, per-dimension normalization over in-range taps.
// ---------------------------------------------------------------------------
__global__ void k_resize_down(const float* __restrict__ in, float* __restrict__ out,
                              int BC, int Hin, int Win, int Hout, int Wout,
                              int f, int doClip)
{
    int idx = blockIdx.x * blockDim.x + threadIdx.x;
    int total = BC * Hout * Wout;
    if (idx >= total) return;
    int ox = idx % Wout;
    int t  = idx / Wout;
    int oy = t % Hout;
    int bc = t / Hout;

    float ff = (float)f;
    float sy = f * oy + 0.5f * (f - 1);
    float sx = f * ox + 0.5f * (f - 1);
    int jy0 = f * oy - f / 2;
    int jx0 = f * ox - f / 2;
    int nt = 2 * f;

    float wy[8], wx[8];
    float sumy = 0.0f, sumx = 0.0f;
    for (int k = 0; k < nt; k++) {
        int jy = jy0 + k;
        float a = (jy >= 0 && jy < Hin) ? (1.0f - fabsf((float)jy - sy) / ff) : 0.0f;
        wy[k] = a; sumy += a;
        int jx = jx0 + k;
        float b = (jx >= 0 && jx < Win) ? (1.0f - fabsf((float)jx - sx) / ff) : 0.0f;
        wx[k] = b; sumx += b;
    }
    float inv = 1.0f / (sumy * sumx);

    const float* base = in + (size_t)bc * Hin * Win;
    float acc = 0.0f;
    for (int ty = 0; ty < nt; ty++) {
        if (wy[ty] == 0.0f) continue;
        int jy = jy0 + ty;
        const float* row = base + (size_t)jy * Win;
        float racc = 0.0f;
        for (int tx = 0; tx < nt; tx++) {
            if (wx[tx] == 0.0f) continue;
            racc += wx[tx] * row[jx0 + tx];
        }
        acc += wy[ty] * racc;
    }
    acc *= inv;
    if (doClip) acc = clamp01f(acc);
    out[idx] = acc;
}

// ---------------------------------------------------------------------------
// down_sparse: valid-mean pooling of DL, max-style ML aggregation
// ---------------------------------------------------------------------------
__global__ void k_down_sparse(const float* __restrict__ DL, const float* __restrict__ ML,
                              float* __restrict__ DLs, float* __restrict__ MLs,
                              int B, int Hin, int Win, int f)
{
    int Hout = Hin / f, Wout = Win / f;
    int idx = blockIdx.x * blockDim.x + threadIdx.x;
    int total = B * Hout * Wout;
    if (idx >= total) return;
    int ox = idx % Wout;
    int t  = idx / Wout;
    int oy = t % Hout;
    int b  = t / Hout;

    const float* DLb = DL + (size_t)b * Hin * Win;
    const float* MLb = ML + (size_t)b * Hin * Win;
    float s = 0.0f, c = 0.0f;
    for (int dy = 0; dy < f; dy++) {
        const float* dr = DLb + (size_t)(oy * f + dy) * Win + ox * f;
        const float* mr = MLb + (size_t)(oy * f + dy) * Win + ox * f;
        for (int dx = 0; dx < f; dx++) {
            float m = mr[dx];
            s += dr[dx] * m;
            c += m;
        }
    }
    MLs[idx] = (c > 0.0f) ? 1.0f : 0.0f;
    DLs[idx] = (c > 0.0f) ? s / (c + 1e-6f) : 0.0f;
}

// ---------------------------------------------------------------------------
// D init at coarsest scale: D = clip(E * 10, 0, 10)
// ---------------------------------------------------------------------------
__global__ void k_initD(const float* __restrict__ Es, float* __restrict__ D, int n)
{
    int idx = blockIdx.x * blockDim.x + threadIdx.x;
    if (idx >= n) return;
    D[idx] = fminf(fmaxf(Es[idx] * 10.0f, 0.0f), 10.0f);
}

// ---------------------------------------------------------------------------
// 2x bilinear upsample (half-pixel, edge-clamped == jax renormalized weights)
// ---------------------------------------------------------------------------
__global__ void k_up2(const float* __restrict__ in, float* __restrict__ out,
                      int B, int Hout, int Wout)
{
    int Hin = Hout / 2, Win = Wout / 2;
    int idx = blockIdx.x * blockDim.x + threadIdx.x;
    int total = B * Hout * Wout;
    if (idx >= total) return;
    int ox = idx % Wout;
    int t  = idx / Wout;
    int oy = t % Hout;
    int b  = t / Hout;

    float sy = 0.5f * (oy + 0.5f) - 0.5f;
    float sx = 0.5f * (ox + 0.5f) - 0.5f;
    int y0 = (int)floorf(sy);
    int x0 = (int)floorf(sx);
    float ay = sy - y0, ax = sx - x0;
    int y0c = max(y0, 0), y1c = min(y0 + 1, Hin - 1);
    int x0c = max(x0, 0), x1c = min(x0 + 1, Win - 1);

    const float* ib = in + (size_t)b * Hin * Win;
    float v00 = ib[(size_t)y0c * Win + x0c];
    float v01 = ib[(size_t)y0c * Win + x1c];
    float v10 = ib[(size_t)y1c * Win + x0c];
    float v11 = ib[(size_t)y1c * Win + x1c];
    out[idx] = (1.0f - ay) * ((1.0f - ax) * v00 + ax * v01)
             + ay          * ((1.0f - ax) * v10 + ax * v11);
}

// ---------------------------------------------------------------------------
// Edge-aware blend of upsampled prev with P_s
// ---------------------------------------------------------------------------
__global__ void k_blend(const float* __restrict__ up, const float* __restrict__ Es,
                        float* __restrict__ D, int B, int H, int W)
{
    int idx = blockIdx.x * blockDim.x + threadIdx.x;
    int total = B * H * W;
    if (idx >= total) return;
    int x = idx % W;
    int t = idx / W;
    int y = t % H;

    float E = Es[idx];
    float gx = (x > 0) ? (E - Es[idx - 1]) : 0.0f;
    float gy = (y > 0) ? (E - Es[idx - W]) : 0.0f;
    float g = clamp01f(0.5f * (fabsf(gx) + fabsf(gy)));
    float w = 0.7f * clamp01f(1.0f - g * 10.0f);   // EDGE_TAU=0.1, GAMMA=1
    float P = fminf(fmaxf(E * 10.0f, 0.0f), 10.0f);
    D[idx] = w * up[idx] + (1.0f - w) * P;
}

// ---------------------------------------------------------------------------
// Build 6-channel encoder input x = [I(3), DL, ML, E]
// ---------------------------------------------------------------------------
__global__ void k_make_x(const float* __restrict__ I, const float* __restrict__ DL,
                         const float* __restrict__ ML, const float* __restrict__ E,
                         float* __restrict__ X, int B, int npx)
{
    int idx = blockIdx.x * blockDim.x + threadIdx.x;
    int total = B * 6 * npx;
    if (idx >= total) return;
    int p  = idx % npx;
    int t  = idx / npx;
    int ch = t % 6;
    int b  = t / 6;
    float v;
    if (ch < 3)      v = I [((size_t)b * 3 + ch) * npx + p];
    else if (ch == 3) v = DL[(size_t)b * npx + p];
    else if (ch == 4) v = ML[(size_t)b * npx + p];
    else              v = E [(size_t)b * npx + p];
    X[idx] = v;
}

// ---------------------------------------------------------------------------
// kap_in = [feat(64), D/10]
// ---------------------------------------------------------------------------
__global__ void k_make_kapin(const float* __restrict__ feat, const float* __restrict__ D,
                             float* __restrict__ kap, int B, int npx)
{
    int idx = blockIdx.x * blockDim.x + threadIdx.x;
    int total = B * 65 * npx;
    if (idx >= total) return;
    int p  = idx % npx;
    int t  = idx / npx;
    int ch = t % 65;
    int b  = t / 65;
    kap[idx] = (ch < 64) ? feat[((size_t)b * 64 + ch) * npx + p]
                         : D[(size_t)b * npx + p] * 0.1f;
}

// ---------------------------------------------------------------------------
// Direct 3x3 conv, 'SAME' zero pad, NCHW/OIHW.
// Block: 32x8 spatial tile; each thread 4 positions x CT out-channels.
// NTH = (COUT/CT)*64.   ACT: 0=none, 1=relu.
// ---------------------------------------------------------------------------
template<int CIN, int COUT, int CT, int ACT, int NTH>
__global__ __launch_bounds__(NTH)
void k_conv3(const float* __restrict__ in, const float* __restrict__ wgt,
             const float* __restrict__ bias, float* __restrict__ out,
             int H, int W)
{
    constexpr int CH = 8;
    constexpr int TW = 32, TH = 8, PW = 36;
    __shared__ __align__(16) float sp[CH][TH + 2][PW];
    __shared__ float sw[CH][9][COUT];

    const int tid = threadIdx.x;
    const int q  = tid & 63;
    const int g  = tid >> 6;
    const int r  = q >> 3;
    const int xb = (q & 7) * 4;
    const int b  = blockIdx.z;
    const int x0 = blockIdx.x * TW;
    const int y0 = blockIdx.y * TH;

    float acc[CT][4];
#pragma unroll
    for (int c = 0; c < CT; c++) {
        acc[c][0] = 0.0f; acc[c][1] = 0.0f; acc[c][2] = 0.0f; acc[c][3] = 0.0f;
    }

    const float* inb = in + (size_t)b * CIN * H * W;

    for (int c0 = 0; c0 < CIN; c0 += CH) {
        int cc = min(CH, CIN - c0);
        // input patch: cc x 10 x 34 (origin y0-1, x0-1), zero pad outside
        for (int i = tid; i < cc * 10 * 34; i += NTH) {
            int ci  = i / 340;
            int rem = i - ci * 340;
            int py  = rem / 34;
            int px  = rem - py * 34;
            int gy = y0 - 1 + py;
            int gx = x0 - 1 + px;
            float v = 0.0f;
            if (gy >= 0 && gy < H && gx >= 0 && gx < W)
                v = inb[(size_t)(c0 + ci) * H * W + (size_t)gy * W + gx];
            sp[ci][py][px] = v;
        }
        // weights chunk -> sw[ci][tap][co]
        for (int i = tid; i < cc * 9 * COUT; i += NTH) {
            int co  = i % COUT;
            int t2  = i / COUT;
            int tap = t2 % 9;
            int ci  = t2 / 9;
            sw[ci][tap][co] = wgt[((size_t)co * CIN + (c0 + ci)) * 9 + tap];
        }
        __syncthreads();

        for (int ci = 0; ci < cc; ci++) {
#pragma unroll
            for (int ky = 0; ky < 3; ky++) {
                const float* row = &sp[ci][r + ky][xb];
                float4 v4 = *(const float4*)row;
                float2 v2 = *(const float2*)(row + 4);
                float xv[6] = {v4.x, v4.y, v4.z, v4.w, v2.x, v2.y};
#pragma unroll
                for (int kx = 0; kx < 3; kx++) {
                    const float* wrow = &sw[ci][ky * 3 + kx][g * CT];
#pragma unroll
                    for (int c = 0; c < CT; c++) {
                        float wv = wrow[c];
                        acc[c][0] += xv[kx + 0] * wv;
                        acc[c][1] += xv[kx + 1] * wv;
                        acc[c][2] += xv[kx + 2] * wv;
                        acc[c][3] += xv[kx + 3] * wv;
                    }
                }
            }
        }
        __syncthreads();
    }

    float* outb = out + (size_t)b * COUT * H * W;
#pragma unroll
    for (int c = 0; c < CT; c++) {
        int co = g * CT + c;
        float bv = bias[co];
        float* op = outb + (size_t)co * H * W + (size_t)(y0 + r) * W + x0 + xb;
#pragma unroll
        for (int p = 0; p < 4; p++) {
            float v = acc[c][p] + bv;
            if (ACT == 1) v = fmaxf(v, 0.0f);
            op[p] = v;
        }
    }
}

// ---------------------------------------------------------------------------
// Post: affinity normalize + center; write packed [A(24), center(3)]
// ---------------------------------------------------------------------------
__global__ void k_post_aff(const float* __restrict__ Araw, float* __restrict__ pack,
                           int B, int npx)
{
    int idx = blockIdx.x * blockDim.x + threadIdx.x;
    int total = B * npx;
    if (idx >= total) return;
    int b = idx / npx;
    int p = idx - b * npx;
    const float* Ab = Araw + (size_t)b * 24 * npx + p;
    float a[24];
#pragma unroll
    for (int n = 0; n < 24; n++) a[n] = Ab[(size_t)n * npx];
    float* pkb = pack + (size_t)idx * 36;
#pragma unroll
    for (int k = 0; k < 3; k++) {
        float sa = 0.0f;
#pragma unroll
        for (int n = 0; n < 8; n++) sa += fabsf(a[k * 8 + n]);
        float inv = 1.0f / (sa + 1e-6f);
        float ssum = 0.0f;
#pragma unroll
        for (int n = 0; n < 8; n++) {
            float v = a[k * 8 + n] * inv;
            pkb[k * 8 + n] = v;
            ssum += v;
        }
        pkb[24 + k] = 1.0f - ssum;
    }
}

// Post: gate softmax over K=3 -> packed [27..29]
__global__ void k_post_gate(const float* __restrict__ raw, float* __restrict__ pack,
                            int B, int npx)
{
    int idx = blockIdx.x * blockDim.x + threadIdx.x;
    int total = B * npx;
    if (idx >= total) return;
    int b = idx / npx;
    int p = idx - b * npx;
    const float* rb = raw + (size_t)b * 3 * npx + p;
    float v0 = rb[0], v1 = rb[(size_t)npx], v2 = rb[(size_t)2 * npx];
    float m = fmaxf(v0, fmaxf(v1, v2));
    float e0 = expf(v0 - m), e1 = expf(v1 - m), e2 = expf(v2 - m);
    float inv = 1.0f / (e0 + e1 + e2);
    float* pkb = pack + (size_t)idx * 36;
    pkb[27] = e0 * inv; pkb[28] = e1 * inv; pkb[29] = e2 * inv;
}

// Post: kappa = 0.1 + 0.9 * sigmoid(raw) -> packed [30..32]
__global__ void k_post_curv(const float* __restrict__ raw, float* __restrict__ pack,
                            int B, int npx)
{
    int idx = blockIdx.x * blockDim.x + threadIdx.x;
    int total = B * npx;
    if (idx >= total) return;
    int b = idx / npx;
    int p = idx - b * npx;
    const float* rb = raw + (size_t)b * 3 * npx + p;
    float* pkb = pack + (size_t)idx * 36;
#pragma unroll
    for (int k = 0; k < 3; k++) {
        float v = rb[(size_t)k * npx];
        pkb[30 + k] = 0.1f + 0.9f / (1.0f + expf(-v));
    }
}

// ---------------------------------------------------------------------------
// One CSPN propagation step. 32x8 tile, smem D patch with halo 4 (max dil).
// Packed params per pixel: [A(24), center(3), sigma(3), kappa(3), pad(3)]
// ---------------------------------------------------------------------------
__global__ __launch_bounds__(256)
void k_prop(const float* __restrict__ D, const float* __restrict__ pack,
            const float* __restrict__ DLs, const float* __restrict__ MLs,
            float* __restrict__ Dout, int H, int W)
{
    __shared__ float sD[16][40];
    int b  = blockIdx.z;
    int x0 = blockIdx.x * 32;
    int y0 = blockIdx.y * 8;
    const float* Db = D + (size_t)b * H * W;
    int tid = threadIdx.x;

    for (int i = tid; i < 16 * 40; i += 256) {
        int py = i / 40, px = i - (i / 40) * 40;
        int gy = y0 - 4 + py, gx = x0 - 4 + px;
        sD[py][px] = (gy >= 0 && gy < H && gx >= 0 && gx < W) ? Db[(size_t)gy * W + gx] : 0.0f;
    }
    __syncthreads();

    int lx = tid & 31, ly = tid >> 5;
    int gx = x0 + lx, gy = y0 + ly;
    size_t pix = (size_t)b * H * W + (size_t)gy * W + gx;

    float d = sD[ly + 4][lx + 4];
    const float4* pk4 = (const float4*)(pack + pix * 36);
    float4 P[9];
#pragma unroll
    for (int i = 0; i < 9; i++) P[i] = pk4[i];
    const float* A = (const float*)P;

    float mix = 0.0f;
#pragma unroll
    for (int k = 0; k < 3; k++) {
        int dil = 1 << k;   // 1, 2, 4
        float agg = A[24 + k] * d;
        agg += A[k * 8 + 0] * sD[ly + 4 - dil][lx + 4 - dil];
        agg += A[k * 8 + 1] * sD[ly + 4 - dil][lx + 4      ];
        agg += A[k * 8 + 2] * sD[ly + 4 - dil][lx + 4 + dil];
        agg += A[k * 8 + 3] * sD[ly + 4      ][lx + 4 - dil];
        agg += A[k * 8 + 4] * sD[ly + 4      ][lx + 4 + dil];
        agg += A[k * 8 + 5] * sD[ly + 4 + dil][lx + 4 - dil];
        agg += A[k * 8 + 6] * sD[ly + 4 + dil][lx + 4      ];
        agg += A[k * 8 + 7] * sD[ly + 4 + dil][lx + 4 + dil];
        mix += A[27 + k] * (d + A[30 + k] * (agg - d));
    }
    float ml = MLs[pix];
    float dl = DLs[pix];
    Dout[pix] = ml * (0.9f * dl + 0.1f * mix) + (1.0f - ml) * mix;
}

// ---------------------------------------------------------------------------
// Host orchestration
// ---------------------------------------------------------------------------
extern "C" void kernel_launch(void* const* d_in, const int* in_sizes, int n_in,
                              void* d_out, int out_size)
{
    const float* I   = (const float*)d_in[0];
    const float* DL  = (const float*)d_in[1];
    const float* ML  = (const float*)d_in[2];
    const float* E   = (const float*)d_in[3];
    const float* ew0 = (const float*)d_in[4];
    const float* eb0 = (const float*)d_in[5];
    const float* ew1 = (const float*)d_in[6];
    const float* eb1 = (const float*)d_in[7];
    const float* ew2 = (const float*)d_in[8];
    const float* eb2 = (const float*)d_in[9];
    const float* aw  = (const float*)d_in[10];
    const float* ab  = (const float*)d_in[11];
    const float* gw  = (const float*)d_in[12];
    const float* gb  = (const float*)d_in[13];
    const float* cw  = (const float*)d_in[14];
    const float* cb  = (const float*)d_in[15];

    int B = in_sizes[0] / (3 * HF * WF);
    if (B > B_MAX) B = B_MAX;

    float *pIs, *pEs, *pDLs, *pMLs, *pD0, *pD1, *pUp, *pX, *pF1, *pF2, *pKap, *pA, *pT3, *pPk;
    cudaGetSymbolAddress((void**)&pIs,  g_Is);
    cudaGetSymbolAddress((void**)&pEs,  g_Es);
    cudaGetSymbolAddress((void**)&pDLs, g_DLs);
    cudaGetSymbolAddress((void**)&pMLs, g_MLs);
    cudaGetSymbolAddress((void**)&pD0,  g_D0);
    cudaGetSymbolAddress((void**)&pD1,  g_D1);
    cudaGetSymbolAddress((void**)&pUp,  g_up);
    cudaGetSymbolAddress((void**)&pX,   g_x);
    cudaGetSymbolAddress((void**)&pF1,  g_f1);
    cudaGetSymbolAddress((void**)&pF2,  g_f2);
    cudaGetSymbolAddress((void**)&pKap, g_kap);
    cudaGetSymbolAddress((void**)&pA,   g_A);
    cudaGetSymbolAddress((void**)&pT3,  g_t3);
    cudaGetSymbolAddress((void**)&pPk,  g_pk);

    const int scales[3] = {4, 2, 1};

    for (int si = 0; si < 3; si++) {
        int s   = scales[si];
        int Hs  = HF / s, Ws = WF / s;
        int npx = Hs * Ws;
        int n1  = B * npx;
        int blk1 = (n1 + 255) / 256;

        const float *Isp, *Esp, *DLp, *MLp;
        if (s > 1) {
            int nI = B * 3 * npx;
            k_resize_down<<<(nI + 255) / 256, 256>>>(I, pIs, B * 3, HF, WF, Hs, Ws, s, 0);
            k_resize_down<<<blk1, 256>>>(E, pEs, B, HF, WF, Hs, Ws, s, 1);
            k_down_sparse<<<blk1, 256>>>(DL, ML, pDLs, pMLs, B, HF, WF, s);
            Isp = pIs; Esp = pEs; DLp = pDLs; MLp = pMLs;
        } else {
            Isp = I; Esp = E; DLp = DL; MLp = ML;
        }

        if (si == 0) {
            k_initD<<<blk1, 256>>>(Esp, pD0, n1);
        } else {
            k_up2<<<blk1, 256>>>(pD0, pUp, B, Hs, Ws);
            k_blend<<<blk1, 256>>>(pUp, Esp, pD0, B, Hs, Ws);
        }

        int n6 = B * 6 * npx;
        k_make_x<<<(n6 + 255) / 256, 256>>>(Isp, DLp, MLp, Esp, pX, B, npx);

        dim3 cg(Ws / 32, Hs / 8, B);
        k_conv3<6,  64, 16, 1, 256><<<cg, 256>>>(pX,  ew0, eb0, pF1, Hs, Ws);
        k_conv3<64, 64, 16, 1, 256><<<cg, 256>>>(pF1, ew1, eb1, pF2, Hs, Ws);
        k_conv3<64, 64, 16, 1, 256><<<cg, 256>>>(pF2, ew2, eb2, pF1, Hs, Ws);  // feat

        k_conv3<64, 24, 6, 0, 256><<<cg, 256>>>(pF1, aw, ab, pA, Hs, Ws);
        k_post_aff<<<blk1, 256>>>(pA, pPk, B, npx);

        k_conv3<64, 3, 3, 0, 64><<<cg, 64>>>(pF1, gw, gb, pT3, Hs, Ws);
        k_post_gate<<<blk1, 256>>>(pT3, pPk, B, npx);

        int n65 = B * 65 * npx;
        k_make_kapin<<<(n65 + 255) / 256, 256>>>(pF1, pD0, pKap, B, npx);
        k_conv3<65, 3, 3, 0, 64><<<cg, 64>>>(pKap, cw, cb, pT3, Hs, Ws);
        k_post_curv<<<blk1, 256>>>(pT3, pPk, B, npx);

        // 6 propagation steps (ping-pong; ends back in pD0)
        float* Dc = pD0;
        float* Dn = pD1;
        for (int st = 0; st < 6; st++) {
            float* dst = Dn;
            if (si == 2 && st == 5) dst = (float*)d_out;   // final result
            k_prop<<<cg, 256>>>(Dc, pPk, DLp, MLp, dst, Hs, Ws);
            Dc = dst;
            Dn = (Dc == pD0) ? pD1 : pD0;
        }
    }
}